// round 12
// baseline (speedup 1.0000x reference)
#include <cuda_runtime.h>

// MultiScaleRoIAlign: 4-level FPN, RoIAlign(aligned=False), OUT=7, SR=2.
// feats: [2,256,200,200],[2,256,100,100],[2,256,50,50],[2,256,25,25] fp32
// boxes: [2,256,4] fp32 -> out: [512,256,7,7] fp32
//
// v12: v11 (grid 2048, warp-pair channel streams, x2 channel unroll, ONE
// register geometry set per warp) + __launch_bounds__(256, 3) to cap regs
// at 85 and lift residency from 2 to 3 blocks/SM (16 -> 24 warps). L1 was
// at 57.6% with issue 29% -- more warps push L1 toward its roofline.

#define NLVL 4

__global__ __launch_bounds__(256, 3) void roi_align_kernel(
    const float* __restrict__ f0, const float* __restrict__ f1,
    const float* __restrict__ f2, const float* __restrict__ f3,
    const float* __restrict__ boxes, float* __restrict__ out)
{
    const int blk   = blockIdx.x;
    const int r     = blk >> 2;        // roi 0..511
    const int cq    = blk & 3;         // channel quarter: 64 channels
    const int tid   = threadIdx.x;
    const int w     = tid >> 5;        // warp 0..7
    const int pair  = w >> 1;          // channel stream 0..3 (16 ch each)
    const int half  = w & 1;           // 0: bins 0..31, 1: bins 32..48
    const int lane  = tid & 31;
    const int b     = r >> 8;

    // ---- per-RoI geometry ----
    const float bx1 = boxes[r * 4 + 0];
    const float by1 = boxes[r * 4 + 1];
    const float bx2 = boxes[r * 4 + 2];
    const float by2 = boxes[r * 4 + 3];

    const float area = (bx2 - bx1) * (by2 - by1);
    float lv = floorf(4.0f + log2f(sqrtf(area) / 224.0f + 1e-6f));
    lv = fminf(fmaxf(lv, 2.0f), 5.0f);
    const int level = (int)lv - 2;

    const int   Htab[NLVL]  = {200, 100, 50, 25};
    const float sctab[NLVL] = {0.25f, 0.125f, 0.0625f, 0.03125f};
    const int   H  = Htab[level];
    const int   W  = H;
    const float sc = sctab[level];
    const float* feat = (level == 0) ? f0 : (level == 1) ? f1 : (level == 2) ? f2 : f3;

    const float x1 = bx1 * sc, y1 = by1 * sc;
    const float roi_w = fmaxf(bx2 * sc - x1, 1.0f);
    const float roi_h = fmaxf(by2 * sc - y1, 1.0f);
    const float bin_w = roi_w / 7.0f;
    const float bin_h = roi_h / 7.0f;

    // ---- this lane's bin ----
    const int  bin_raw = half * 32 + lane;
    const bool live    = (bin_raw < 49);
    const int  bin     = live ? bin_raw : 0;
    const int  ph = bin / 7;
    const int  pw = bin - 7 * ph;

    // ---- per-lane bin geometry: ONE set, in registers ----
    int   Ry[4], Xc[4];
    float Cy[4], Cx[4];

    #pragma unroll
    for (int s = 0; s < 2; s++) {
        // y tap (jy = 2*ph + s)
        {
            const float g   = (float)ph + ((float)s + 0.5f) * 0.5f;
            float pos = y1 + g * bin_h;
            const float vld = (pos >= -1.0f && pos <= (float)H) ? 0.25f : 0.0f; // fold /4
            pos = fmaxf(pos, 0.0f);
            int lo = (int)pos, hi;
            if (lo >= H - 1) { lo = H - 1; hi = H - 1; pos = (float)lo; }
            else             { hi = lo + 1; }
            const float fr = pos - (float)lo;
            Ry[2 * s + 0] = lo * W;
            Ry[2 * s + 1] = hi * W;
            Cy[2 * s + 0] = vld * (1.0f - fr);
            Cy[2 * s + 1] = vld * fr;
        }
        // x tap (jx = 2*pw + s)
        {
            const float g   = (float)pw + ((float)s + 0.5f) * 0.5f;
            float pos = x1 + g * bin_w;
            const float vld = (pos >= -1.0f && pos <= (float)W) ? 1.0f : 0.0f;
            pos = fmaxf(pos, 0.0f);
            int lo = (int)pos, hi;
            if (lo >= W - 1) { lo = W - 1; hi = W - 1; pos = (float)lo; }
            else             { hi = lo + 1; }
            const float fr = pos - (float)lo;
            Xc[2 * s + 0] = lo;
            Xc[2 * s + 1] = hi;
            Cx[2 * s + 0] = vld * (1.0f - fr);
            Cx[2 * s + 1] = vld * fr;
        }
    }

    // ---- sweep 16 channels per warp pair, x2 unrolled ----
    const size_t plane = (size_t)H * W;
    const int c0 = cq * 64 + pair * 16;
    const float* fp = feat + ((size_t)b * 256 + c0) * plane;
    float* op = out + ((size_t)r * 256 + c0) * 49 + bin;

    if (live) {
        #pragma unroll 1
        for (int k = 0; k < 16; k += 2) {
            const float* fpa = fp;
            const float* fpb = fp + plane;
            float acc_a = 0.0f, acc_b = 0.0f;
            #pragma unroll
            for (int i = 0; i < 4; i++) {
                const float* A = fpa + Ry[i];
                const float* B = fpb + Ry[i];
                acc_a += Cy[i] * (Cx[0] * A[Xc[0]] + Cx[1] * A[Xc[1]]
                                + Cx[2] * A[Xc[2]] + Cx[3] * A[Xc[3]]);
                acc_b += Cy[i] * (Cx[0] * B[Xc[0]] + Cx[1] * B[Xc[1]]
                                + Cx[2] * B[Xc[2]] + Cx[3] * B[Xc[3]]);
            }
            op[0]  = acc_a;
            op[49] = acc_b;
            fp += 2 * plane;
            op += 2 * 49;
        }
    }
}

extern "C" void kernel_launch(void* const* d_in, const int* in_sizes, int n_in,
                              void* d_out, int out_size) {
    const int nroi = in_sizes[4] / 4;   // 512
    roi_align_kernel<<<nroi * 4, 256>>>(
        (const float*)d_in[0], (const float*)d_in[1],
        (const float*)d_in[2], (const float*)d_in[3],
        (const float*)d_in[4], (float*)d_out);
}

// round 13
// speedup vs baseline: 1.1245x; 1.1245x over previous
#include <cuda_runtime.h>

// MultiScaleRoIAlign: 4-level FPN, RoIAlign(aligned=False), OUT=7, SR=2.
// feats: [2,256,200,200],[2,256,100,100],[2,256,50,50],[2,256,25,25] fp32
// boxes: [2,256,4] fp32 -> out: [512,256,7,7] fp32
//
// v13: one-row-per-LDG mapping. grid = 2048 (4 blocks/RoI, 64 channels
// each), block = 224 threads = 7 warps. Warp = output bin-row ph; lane =
// (pw = lane>>2, x-tap j = lane&3). The 4 y-tap row offsets are warp-
// uniform, so every LDG reads ONE feature row at <=28 nearby columns
// (1-2 L1 wavefronts vs ~5-10 for the lane=bin mapping). Two shfl_xor
// reduce the 4 x-taps of each bin; lane j==0 stores. x2 channel unroll.

#define NLVL 4

__global__ __launch_bounds__(224) void roi_align_kernel(
    const float* __restrict__ f0, const float* __restrict__ f1,
    const float* __restrict__ f2, const float* __restrict__ f3,
    const float* __restrict__ boxes, float* __restrict__ out)
{
    const int blk  = blockIdx.x;
    const int r    = blk >> 2;         // roi 0..511
    const int cq   = blk & 3;          // channel quarter (64 ch)
    const int tid  = threadIdx.x;
    const int ph   = tid >> 5;         // warp 0..6 = bin row
    const int lane = tid & 31;
    const int b    = r >> 8;

    // ---- per-RoI geometry ----
    const float bx1 = boxes[r * 4 + 0];
    const float by1 = boxes[r * 4 + 1];
    const float bx2 = boxes[r * 4 + 2];
    const float by2 = boxes[r * 4 + 3];

    const float area = (bx2 - bx1) * (by2 - by1);
    float lvf = floorf(4.0f + log2f(sqrtf(area) / 224.0f + 1e-6f));
    lvf = fminf(fmaxf(lvf, 2.0f), 5.0f);
    const int level = (int)lvf - 2;

    const int   Htab[NLVL]  = {200, 100, 50, 25};
    const float sctab[NLVL] = {0.25f, 0.125f, 0.0625f, 0.03125f};
    const int   H  = Htab[level];
    const int   W  = H;
    const float sc = sctab[level];
    const float* feat = (level == 0) ? f0 : (level == 1) ? f1 : (level == 2) ? f2 : f3;

    const float x1 = bx1 * sc, y1 = by1 * sc;
    const float roi_w = fmaxf(bx2 * sc - x1, 1.0f);
    const float roi_h = fmaxf(by2 * sc - y1, 1.0f);
    const float bin_w = roi_w / 7.0f;
    const float bin_h = roi_h / 7.0f;

    // ---- warp-uniform y geometry for this ph: 4 rows + folded weights ----
    int   Ry[4];
    float CyW[4];
    #pragma unroll
    for (int s = 0; s < 2; s++) {
        const float g = (float)ph + ((float)s + 0.5f) * 0.5f;
        float pos = y1 + g * bin_h;
        const float vld = (pos >= -1.0f && pos <= (float)H) ? 0.25f : 0.0f;  // fold /4
        pos = fmaxf(pos, 0.0f);
        int lo = (int)pos, hi;
        if (lo >= H - 1) { lo = H - 1; hi = H - 1; pos = (float)lo; }
        else             { hi = lo + 1; }
        const float fr = pos - (float)lo;
        Ry[2 * s + 0] = lo * W;
        Ry[2 * s + 1] = hi * W;
        CyW[2 * s + 0] = vld * (1.0f - fr);
        CyW[2 * s + 1] = vld * fr;
    }

    // ---- per-lane x geometry: pw = lane>>2, j = lane&3 -> (sample, side) ----
    const int  pw   = lane >> 2;
    const int  j    = lane & 3;
    const bool live = (pw < 7);
    int   col = 0;
    float cxw = 0.0f;
    if (live) {
        const int sx   = j >> 1;
        const int side = j & 1;
        const float g = (float)pw + ((float)sx + 0.5f) * 0.5f;
        float pos = x1 + g * bin_w;
        const float vld = (pos >= -1.0f && pos <= (float)W) ? 1.0f : 0.0f;
        pos = fmaxf(pos, 0.0f);
        int lo = (int)pos, hi;
        if (lo >= W - 1) { lo = W - 1; hi = W - 1; pos = (float)lo; }
        else             { hi = lo + 1; }
        const float fr = pos - (float)lo;
        col = side ? hi : lo;
        cxw = vld * (side ? fr : (1.0f - fr));
    }

    const bool storer = live && (j == 0);

    // ---- sweep 64 channels, x2 unrolled ----
    const size_t plane = (size_t)H * W;
    const int c0 = cq * 64;
    const float* fp = feat + ((size_t)b * 256 + c0) * plane;
    float* op = out + ((size_t)r * 256 + c0) * 49 + ph * 7;

    #pragma unroll 1
    for (int k = 0; k < 64; k += 2) {
        const float* A = fp;
        const float* B = fp + plane;

        float ta = 0.0f, tb = 0.0f;
        if (live) {
            ta = cxw * (CyW[0] * A[Ry[0] + col] + CyW[1] * A[Ry[1] + col]
                      + CyW[2] * A[Ry[2] + col] + CyW[3] * A[Ry[3] + col]);
            tb = cxw * (CyW[0] * B[Ry[0] + col] + CyW[1] * B[Ry[1] + col]
                      + CyW[2] * B[Ry[2] + col] + CyW[3] * B[Ry[3] + col]);
        }
        // reduce the 4 x-taps of each bin (xor stays within aligned quads)
        ta += __shfl_xor_sync(0xFFFFFFFFu, ta, 1);
        ta += __shfl_xor_sync(0xFFFFFFFFu, ta, 2);
        tb += __shfl_xor_sync(0xFFFFFFFFu, tb, 1);
        tb += __shfl_xor_sync(0xFFFFFFFFu, tb, 2);

        if (storer) {
            op[pw]      = ta;
            op[49 + pw] = tb;
        }
        fp += 2 * plane;
        op += 2 * 49;
    }
}

extern "C" void kernel_launch(void* const* d_in, const int* in_sizes, int n_in,
                              void* d_out, int out_size) {
    const int nroi = in_sizes[4] / 4;   // 512
    roi_align_kernel<<<nroi * 4, 224>>>(
        (const float*)d_in[0], (const float*)d_in[1],
        (const float*)d_in[2], (const float*)d_in[3],
        (const float*)d_in[4], (float*)d_out);
}